// round 4
// baseline (speedup 1.0000x reference)
#include <cuda_runtime.h>

// Problem constants (fixed shapes from reference_code)
#define BB 2
#define SS 2048
#define DM 1024
#define NH 16
#define HD 64
#define MTOT (BB * SS)   // 4096

// Scratch for projected Q/K/V (static device arrays: allocation-free)
__device__ float g_Qp[MTOT * DM];
__device__ float g_Kp[MTOT * DM];
__device__ float g_Vp[MTOT * DM];

// ---------------------------------------------------------------------------
// Fused projection GEMMs: z = 0/1/2 selects (q,Wq,Qp)/(k,Wk,Kp)/(v,Wv,Vp).
// C[4096,1024] = A[4096,1024] @ W[1024,1024]
// 128x128 CTA tile, BK=8, 256 threads, 8x8 microtile, register double-buffer
// of the global-load fragments.
// ---------------------------------------------------------------------------
__global__ __launch_bounds__(256)
void proj_gemm_fused(const float* __restrict__ q, const float* __restrict__ k,
                     const float* __restrict__ v, const float* __restrict__ Wq,
                     const float* __restrict__ Wk, const float* __restrict__ Wv,
                     float* __restrict__ Qp, float* __restrict__ Kp,
                     float* __restrict__ Vp) {
    __shared__ float As[8][128];
    __shared__ float Bs[8][128];

    const float* A;
    const float* W;
    float* C;
    if (blockIdx.z == 0)      { A = q; W = Wq; C = Qp; }
    else if (blockIdx.z == 1) { A = k; W = Wk; C = Kp; }
    else                      { A = v; W = Wv; C = Vp; }

    const int tid = threadIdx.x;
    const int tx = tid & 15;        // N microtile
    const int ty = tid >> 4;        // M microtile
    const int bm = blockIdx.y * 128;
    const int bn = blockIdx.x * 128;

    const int arow = tid >> 1;            // 0..127
    const int acol = (tid & 1) * 4;       // 0 or 4
    const int brow = tid >> 5;            // 0..7
    const int bcol = (tid & 31) * 4;      // 0..124

    const float* Aptr = A + (size_t)(bm + arow) * DM + acol;
    const float* Wptr = W + (size_t)brow * DM + bn + bcol;

    float acc[8][8];
#pragma unroll
    for (int i = 0; i < 8; i++)
#pragma unroll
        for (int j = 0; j < 8; j++) acc[i][j] = 0.f;

    // prefetch first fragments
    float4 a_nxt = *(const float4*)(Aptr);
    float4 b_nxt = *(const float4*)(Wptr);

    for (int k0 = 0; k0 < DM; k0 += 8) {
        As[acol + 0][arow] = a_nxt.x;
        As[acol + 1][arow] = a_nxt.y;
        As[acol + 2][arow] = a_nxt.z;
        As[acol + 3][arow] = a_nxt.w;
        *(float4*)&Bs[brow][bcol] = b_nxt;
        __syncthreads();

        if (k0 + 8 < DM) {   // prefetch next fragments during compute
            a_nxt = *(const float4*)(Aptr + k0 + 8);
            b_nxt = *(const float4*)(Wptr + (size_t)(k0 + 8) * DM);
        }

#pragma unroll
        for (int kk = 0; kk < 8; kk++) {
            float a[8], b[8];
            *(float4*)(a)     = *(const float4*)&As[kk][ty * 8];
            *(float4*)(a + 4) = *(const float4*)&As[kk][ty * 8 + 4];
            *(float4*)(b)     = *(const float4*)&Bs[kk][tx * 8];
            *(float4*)(b + 4) = *(const float4*)&Bs[kk][tx * 8 + 4];
#pragma unroll
            for (int i = 0; i < 8; i++)
#pragma unroll
                for (int j = 0; j < 8; j++) acc[i][j] += a[i] * b[j];
        }
        __syncthreads();
    }

#pragma unroll
    for (int i = 0; i < 8; i++) {
        const size_t row = (size_t)(bm + ty * 8 + i);
        float* cp = C + row * DM + bn + tx * 8;
        *(float4*)(cp)     = make_float4(acc[i][0], acc[i][1], acc[i][2], acc[i][3]);
        *(float4*)(cp + 4) = make_float4(acc[i][4], acc[i][5], acc[i][6], acc[i][7]);
    }
}

// ---------------------------------------------------------------------------
// Flash attention: one CTA per (b, h, 64-row q block). 256 threads = 8 warps.
// Warp w owns q rows w*8..w*8+7; lane owns key/out cols lane and lane+32.
// K stored transposed in smem ([d][col]); V natural ([k][c]).
// P kept ENTIRELY in registers: PV uses warp shuffles to broadcast P[row][k],
// eliminating the P smem tile and its broadcast-LDS traffic.
// Smem = 2 * 16KB = 32KB.
// ---------------------------------------------------------------------------
__global__ __launch_bounds__(256, 3)
void attn_kernel(const int* __restrict__ v_mask, float* __restrict__ out) {
    __shared__ float Qst[64 * 64];   // [d][row]   (transposed Q)
    __shared__ float KVs[64 * 64];   // K phase: [d][col]; V phase: [k][c]

    const int tid  = threadIdx.x;
    const int lane = tid & 31;
    const int w    = tid >> 5;        // 0..7
    const int q0   = blockIdx.x * 64;
    const int h    = blockIdx.y;
    const int b    = blockIdx.z;

    const float* Qg = g_Qp + (size_t)(b * SS) * DM + h * HD;
    const float* Kg = g_Kp + (size_t)(b * SS) * DM + h * HD;
    const float* Vg = g_Vp + (size_t)(b * SS) * DM + h * HD;

    // Load Q tile transposed: Qst[d][r] = Q[q0+r][d]
    {
        const int r   = tid >> 2;          // 0..63
        const int seg = (tid & 3) * 16;    // d start
        const float* src = Qg + (size_t)(q0 + r) * DM + seg;
#pragma unroll
        for (int i = 0; i < 4; i++) {
            float4 vv = *(const float4*)(src + i * 4);
            const int d = seg + i * 4;
            Qst[(d + 0) * 64 + r] = vv.x;
            Qst[(d + 1) * 64 + r] = vv.y;
            Qst[(d + 2) * 64 + r] = vv.z;
            Qst[(d + 3) * 64 + r] = vv.w;
        }
    }

    float m_r[8], l_r[8], o0[8], o1[8];
#pragma unroll
    for (int i = 0; i < 8; i++) {
        m_r[i] = -3e38f; l_r[i] = 0.f; o0[i] = 0.f; o1[i] = 0.f;
    }
    __syncthreads();

    for (int kb = 0; kb < SS; kb += 64) {
        // Load K tile transposed: KVs[d][col] = K[kb+col][d]
        {
            const int r   = tid >> 2;
            const int seg = (tid & 3) * 16;
            const float* src = Kg + (size_t)(kb + r) * DM + seg;
#pragma unroll
            for (int i = 0; i < 4; i++) {
                float4 vv = *(const float4*)(src + i * 4);
                const int d = seg + i * 4;
                KVs[(d + 0) * 64 + r] = vv.x;
                KVs[(d + 1) * 64 + r] = vv.y;
                KVs[(d + 2) * 64 + r] = vv.z;
                KVs[(d + 3) * 64 + r] = vv.w;
            }
        }
        const int mk0 = v_mask[b * SS + kb + lane];
        const int mk1 = v_mask[b * SS + kb + lane + 32];
        __syncthreads();

        // S = Q K^T  (per-thread: 8 rows x 2 cols)
        float p0[8], p1[8];
#pragma unroll
        for (int i = 0; i < 8; i++) { p0[i] = 0.f; p1[i] = 0.f; }
#pragma unroll 8
        for (int d = 0; d < 64; d++) {
            float a[8];
            *(float4*)(a)     = *(const float4*)&Qst[d * 64 + w * 8];
            *(float4*)(a + 4) = *(const float4*)&Qst[d * 64 + w * 8 + 4];
            const float b0 = KVs[d * 64 + lane];
            const float b1 = KVs[d * 64 + lane + 32];
#pragma unroll
            for (int i = 0; i < 8; i++) {
                p0[i] += a[i] * b0;
                p1[i] += a[i] * b1;
            }
        }
        // scale + mask (exact -1e12, matching reference's a*m - (1-m)*1e12)
#pragma unroll
        for (int i = 0; i < 8; i++) {
            p0[i] = mk0 ? p0[i] * 0.125f : -1e12f;
            p1[i] = mk1 ? p1[i] * 0.125f : -1e12f;
        }

        // Online softmax (warp-level reductions; stats redundant across lanes).
        // p0/p1 become the probabilities, kept in registers.
#pragma unroll
        for (int i = 0; i < 8; i++) {
            float mx = fmaxf(p0[i], p1[i]);
#pragma unroll
            for (int off = 16; off > 0; off >>= 1)
                mx = fmaxf(mx, __shfl_xor_sync(0xffffffffu, mx, off));
            const float mn   = fmaxf(m_r[i], mx);
            const float corr = __expf(m_r[i] - mn);
            p0[i] = __expf(p0[i] - mn);
            p1[i] = __expf(p1[i] - mn);
            float sum = p0[i] + p1[i];
#pragma unroll
            for (int off = 16; off > 0; off >>= 1)
                sum += __shfl_xor_sync(0xffffffffu, sum, off);
            l_r[i] = l_r[i] * corr + sum;
            m_r[i] = mn;
            o0[i] *= corr;
            o1[i] *= corr;
        }
        __syncthreads();   // all warps done reading K before V overwrite

        // Load V tile natural: KVs[k][c] = V[kb+k][c]
        {
            const int r   = tid >> 2;
            const int seg = (tid & 3) * 16;
            const float* src = Vg + (size_t)(kb + r) * DM + seg;
            float4* dst = (float4*)&KVs[r * 64 + seg];
#pragma unroll
            for (int i = 0; i < 4; i++) dst[i] = *(const float4*)(src + i * 4);
        }
        __syncthreads();

        // O += P @ V  — P broadcast via warp shuffles (no smem P tile).
        // Keys 0..31 live in p0 (lane k), keys 32..63 in p1 (lane k-32).
#pragma unroll 4
        for (int k = 0; k < 32; k++) {
            const float b0 = KVs[k * 64 + lane];
            const float b1 = KVs[k * 64 + lane + 32];
#pragma unroll
            for (int i = 0; i < 8; i++) {
                const float p = __shfl_sync(0xffffffffu, p0[i], k);
                o0[i] += p * b0;
                o1[i] += p * b1;
            }
        }
#pragma unroll 4
        for (int k = 0; k < 32; k++) {
            const float b0 = KVs[(k + 32) * 64 + lane];
            const float b1 = KVs[(k + 32) * 64 + lane + 32];
#pragma unroll
            for (int i = 0; i < 8; i++) {
                const float p = __shfl_sync(0xffffffffu, p1[i], k);
                o0[i] += p * b0;
                o1[i] += p * b1;
            }
        }
        __syncthreads();   // PV reads done before next K load overwrites KVs
    }

    // Epilogue: normalize and write out[b][q][h*64 + c]
#pragma unroll
    for (int i = 0; i < 8; i++) {
        const float inv = 1.0f / l_r[i];
        const int qr = q0 + w * 8 + i;
        float* op = out + (size_t)(b * SS + qr) * DM + h * HD;
        op[lane]      = o0[i] * inv;
        op[lane + 32] = o1[i] * inv;
    }
}

// ---------------------------------------------------------------------------
// Launch: fused projection GEMM grid, then attention.
// ---------------------------------------------------------------------------
extern "C" void kernel_launch(void* const* d_in, const int* in_sizes, int n_in,
                              void* d_out, int out_size) {
    const float* q  = (const float*)d_in[0];
    const float* k  = (const float*)d_in[1];
    const float* v  = (const float*)d_in[2];
    const int*   vm = (const int*)  d_in[3];
    const float* Wq = (const float*)d_in[4];
    const float* Wk = (const float*)d_in[5];
    const float* Wv = (const float*)d_in[6];
    float* out = (float*)d_out;

    float *Qp = nullptr, *Kp = nullptr, *Vp = nullptr;
    cudaGetSymbolAddress((void**)&Qp, g_Qp);
    cudaGetSymbolAddress((void**)&Kp, g_Kp);
    cudaGetSymbolAddress((void**)&Vp, g_Vp);

    dim3 gg(DM / 128, MTOT / 128, 3);  // (8, 32, 3) = 768 CTAs, one launch
    proj_gemm_fused<<<gg, 256>>>(q, k, v, Wq, Wk, Wv, Qp, Kp, Vp);

    dim3 ga(SS / 64, NH, BB);          // (32, 16, 2)
    attn_kernel<<<ga, 256>>>(vm, out);
}

// round 6
// speedup vs baseline: 1.3569x; 1.3569x over previous
#include <cuda_runtime.h>
#include <cuda_bf16.h>
#include <cstdint>

// Problem constants (fixed shapes from reference_code)
#define BB 2
#define SS 2048
#define DM 1024
#define NH 16
#define HD 64
#define MTOT (BB * SS)   // 4096

// Scratch (static device arrays: allocation-free)
__device__ float g_Qp[MTOT * DM];
__device__ float g_Kp[MTOT * DM];
__device__ float g_Vp[MTOT * DM];
// bf16 hi/lo splits: A-side (q,k,v) [3][4096][1024], W^T-side [3][1024][1024]
__device__ __nv_bfloat16 g_Ah[3 * MTOT * DM];
__device__ __nv_bfloat16 g_Al[3 * MTOT * DM];
__device__ __nv_bfloat16 g_WTh[3 * DM * DM];
__device__ __nv_bfloat16 g_WTl[3 * DM * DM];

// ===========================================================================
// PTX helpers
// ===========================================================================
__device__ __forceinline__ uint32_t smem_u32(const void* p) {
    uint32_t a;
    asm("{ .reg .u64 t; cvta.to.shared.u64 t, %1; cvt.u32.u64 %0, t; }"
        : "=r"(a) : "l"(p));
    return a;
}
__device__ __forceinline__ void cp_async16(uint32_t dst, const void* src) {
    asm volatile("cp.async.ca.shared.global [%0], [%1], 16;"
                 :: "r"(dst), "l"(src) : "memory");
}
#define CP_COMMIT() asm volatile("cp.async.commit_group;" ::: "memory")
#define CP_WAIT(n)  asm volatile("cp.async.wait_group %0;" :: "n"(n) : "memory")

__device__ __forceinline__ void ldsm_x4(uint32_t r[4], uint32_t addr) {
    asm volatile("ldmatrix.sync.aligned.m8n8.x4.shared.b16 {%0,%1,%2,%3}, [%4];"
                 : "=r"(r[0]), "=r"(r[1]), "=r"(r[2]), "=r"(r[3]) : "r"(addr));
}
__device__ __forceinline__ void ldsm_x2(uint32_t r[2], uint32_t addr) {
    asm volatile("ldmatrix.sync.aligned.m8n8.x2.shared.b16 {%0,%1}, [%2];"
                 : "=r"(r[0]), "=r"(r[1]) : "r"(addr));
}
__device__ __forceinline__ void mma_bf16(float d[4], const uint32_t a[4],
                                         const uint32_t b[2]) {
    asm volatile(
        "mma.sync.aligned.m16n8k16.row.col.f32.bf16.bf16.f32 "
        "{%0,%1,%2,%3}, {%4,%5,%6,%7}, {%8,%9}, {%0,%1,%2,%3};"
        : "+f"(d[0]), "+f"(d[1]), "+f"(d[2]), "+f"(d[3])
        : "r"(a[0]), "r"(a[1]), "r"(a[2]), "r"(a[3]), "r"(b[0]), "r"(b[1]));
}

// ===========================================================================
// Split pass 1: q/k/v fp32 -> bf16 hi/lo, same layout.
// ===========================================================================
__global__ __launch_bounds__(256)
void split_A(const float* __restrict__ q, const float* __restrict__ k,
             const float* __restrict__ v) {
    const size_t per = (size_t)MTOT * DM / 4;   // float4 count per matrix
    size_t idx = (size_t)blockIdx.x * 256 + threadIdx.x;
    if (idx >= 3 * per) return;
    const int m = (int)(idx / per);
    const size_t off = idx - (size_t)m * per;
    const float4* src = (const float4*)(m == 0 ? q : (m == 1 ? k : v));
    float4 x = src[off];

    __nv_bfloat16 h0 = __float2bfloat16(x.x), h1 = __float2bfloat16(x.y);
    __nv_bfloat16 h2 = __float2bfloat16(x.z), h3 = __float2bfloat16(x.w);
    __nv_bfloat16 l0 = __float2bfloat16(x.x - __bfloat162float(h0));
    __nv_bfloat16 l1 = __float2bfloat16(x.y - __bfloat162float(h1));
    __nv_bfloat16 l2 = __float2bfloat16(x.z - __bfloat162float(h2));
    __nv_bfloat16 l3 = __float2bfloat16(x.w - __bfloat162float(h3));

    __nv_bfloat162* dh = (__nv_bfloat162*)g_Ah;
    __nv_bfloat162* dl = (__nv_bfloat162*)g_Al;
    dh[idx * 2]     = __halves2bfloat162(h0, h1);
    dh[idx * 2 + 1] = __halves2bfloat162(h2, h3);
    dl[idx * 2]     = __halves2bfloat162(l0, l1);
    dl[idx * 2 + 1] = __halves2bfloat162(l2, l3);
}

// ===========================================================================
// Split pass 2: W [K][N] -> W^T [N][K] bf16 hi/lo (tiled smem transpose).
// ===========================================================================
__global__ __launch_bounds__(256)
void split_WT(const float* __restrict__ Wq, const float* __restrict__ Wk,
              const float* __restrict__ Wv) {
    __shared__ float tile[32][33];
    const int z = blockIdx.z;
    const float* W = (z == 0 ? Wq : (z == 1 ? Wk : Wv));
    const int n0 = blockIdx.x * 32;
    const int k0 = blockIdx.y * 32;
    const int tx = threadIdx.x, ty = threadIdx.y;   // (32, 8)

#pragma unroll
    for (int i = 0; i < 4; i++) {
        const int kk = k0 + ty + i * 8;
        tile[ty + i * 8][tx] = W[(size_t)kk * DM + n0 + tx];
    }
    __syncthreads();
    __nv_bfloat16* outh = g_WTh + (size_t)z * DM * DM;
    __nv_bfloat16* outl = g_WTl + (size_t)z * DM * DM;
#pragma unroll
    for (int i = 0; i < 4; i++) {
        const int n = n0 + ty + i * 8;
        const float x = tile[tx][ty + i * 8];
        const __nv_bfloat16 h = __float2bfloat16(x);
        outh[(size_t)n * DM + k0 + tx] = h;
        outl[(size_t)n * DM + k0 + tx] = __float2bfloat16(x - __bfloat162float(h));
    }
}

// ===========================================================================
// Tensor-core projection GEMM (mma.sync bf16 x3 split):
// C[4096,1024] = A @ W, z selects q/k/v. CTA tile 128x128, 256 threads
// (8 warps x 64x32 warp tile), BK=64 bf16, cp.async double buffer.
// Smem arrays: Ah, Al [128][64] and Bh, Bl [128][64] (=W^T rows), row
// stride 144B (pad) - ldmatrix conflict-free.
// ===========================================================================
#define GST   144                     // row stride bytes (64*2 + 16 pad)
#define ARR_B (128 * GST)             // 18432 B per array
#define BUF_B (4 * ARR_B)             // 73728 B per stage
#define GEMM_SMEM (2 * BUF_B)         // 147456

__global__ __launch_bounds__(256)
void gemm_bf16tc(float* __restrict__ Qp, float* __restrict__ Kp,
                 float* __restrict__ Vp) {
    extern __shared__ char smem[];
    const int z = blockIdx.z;
    const __nv_bfloat16* Ah = g_Ah + (size_t)z * MTOT * DM;
    const __nv_bfloat16* Al = g_Al + (size_t)z * MTOT * DM;
    const __nv_bfloat16* Bh = g_WTh + (size_t)z * DM * DM;
    const __nv_bfloat16* Bl = g_WTl + (size_t)z * DM * DM;
    float* C = (z == 0 ? Qp : (z == 1 ? Kp : Vp));

    const int m0 = blockIdx.y * 128;
    const int n0 = blockIdx.x * 128;
    const int tid = threadIdx.x;
    const int lane = tid & 31;
    const int wid = tid >> 5;
    const int wm = (wid & 1) * 64;          // warp m offset in tile
    const int wn = (wid >> 1) * 32;         // warp n offset in tile

    const uint32_t sb = smem_u32(smem);

    // fill mapping: 8 threads per 128B row; 32 rows per pass; 4 passes/array
    const int frow = tid >> 3;              // 0..31
    const int fch = tid & 7;               // 16B chunk

    auto fill = [&](int buf, int kc) {
        const uint32_t b0 = sb + buf * BUF_B;
#pragma unroll
        for (int p = 0; p < 4; p++) {
            const int r = frow + p * 32;
            const uint32_t doff = (uint32_t)(r * GST + fch * 16);
            const size_t ga = (size_t)(m0 + r) * DM + kc + fch * 8;
            const size_t gb = (size_t)(n0 + r) * DM + kc + fch * 8;
            cp_async16(b0 + doff,             Ah + ga);
            cp_async16(b0 + ARR_B + doff,     Al + ga);
            cp_async16(b0 + 2 * ARR_B + doff, Bh + gb);
            cp_async16(b0 + 3 * ARR_B + doff, Bl + gb);
        }
        CP_COMMIT();
    };

    float d[4][4][4];
#pragma unroll
    for (int i = 0; i < 4; i++)
#pragma unroll
        for (int j = 0; j < 4; j++)
#pragma unroll
            for (int r = 0; r < 4; r++) d[i][j][r] = 0.f;

    // per-lane ldmatrix row addressing (byte offsets within an array)
    // A x4 tiles: (mrow0, k0), (mrow0+8, k0), (mrow0, k0+8), (mrow0+8, k0+8)
    const int aj = lane >> 3;                         // tile index 0..3
    const int arow_in = (aj & 1) * 8 + (lane & 7);    // + mrow0
    const int akb = (aj >> 1) * 16;                   // + k0 bytes
    // B x2 tiles: (nrow0, k0), (nrow0, k0+8); lanes 0..15 supply addrs
    const int bj = (lane >> 3) & 1;
    const int brow_in = (lane & 7);                   // + nrow0
    const int bkb = bj * 16;

    fill(0, 0);
    int buf = 0;
    for (int s = 0; s < DM / 64; s++) {
        if (s + 1 < DM / 64) {
            fill(buf ^ 1, (s + 1) * 64);
            CP_WAIT(1);
        } else {
            CP_WAIT(0);
        }
        __syncthreads();

        const uint32_t base = sb + buf * BUF_B;
#pragma unroll
        for (int ks = 0; ks < 4; ks++) {
            const int k0b = ks * 32;    // 16 bf16 = 32 bytes
            uint32_t ah[4][4], al[4][4], bh[4][2], bl[4][2];
#pragma unroll
            for (int mt = 0; mt < 4; mt++) {
                const uint32_t aoff =
                    (uint32_t)((wm + mt * 16 + arow_in) * GST + k0b + akb);
                ldsm_x4(ah[mt], base + aoff);
                ldsm_x4(al[mt], base + ARR_B + aoff);
            }
#pragma unroll
            for (int nt = 0; nt < 4; nt++) {
                const uint32_t boff =
                    (uint32_t)((wn + nt * 8 + brow_in) * GST + k0b + bkb);
                ldsm_x2(bh[nt], base + 2 * ARR_B + boff);
                ldsm_x2(bl[nt], base + 3 * ARR_B + boff);
            }
#pragma unroll
            for (int mt = 0; mt < 4; mt++)
#pragma unroll
                for (int nt = 0; nt < 4; nt++) {
                    mma_bf16(d[mt][nt], ah[mt], bh[nt]);   // Ah*Bh
                    mma_bf16(d[mt][nt], ah[mt], bl[nt]);   // Ah*Bl
                    mma_bf16(d[mt][nt], al[mt], bh[nt]);   // Al*Bh
                }
        }
        __syncthreads();
        buf ^= 1;
    }

    // epilogue: c0:(g,2t) c1:(g,2t+1) c2:(g+8,2t) c3:(g+8,2t+1)
    const int g = lane >> 2;
    const int t2 = (lane & 3) * 2;
#pragma unroll
    for (int mt = 0; mt < 4; mt++) {
#pragma unroll
        for (int nt = 0; nt < 4; nt++) {
            const int row0 = m0 + wm + mt * 16 + g;
            const int col = n0 + wn + nt * 8 + t2;
            *(float2*)(C + (size_t)row0 * DM + col) =
                make_float2(d[mt][nt][0], d[mt][nt][1]);
            *(float2*)(C + (size_t)(row0 + 8) * DM + col) =
                make_float2(d[mt][nt][2], d[mt][nt][3]);
        }
    }
}

// ===========================================================================
// Flash attention (fp32, smem P) with float4 PV loop.
// One CTA per (b, h, 64 q rows). 256 threads = 8 warps; warp w owns rows
// w*8..w*8+7; lane owns key/out cols lane and lane+32. Smem 48KB.
// ===========================================================================
__global__ __launch_bounds__(256)
void attn_kernel(const int* __restrict__ v_mask, float* __restrict__ out) {
    __shared__ float Qst[64 * 64];   // [d][row]   (transposed Q)
    __shared__ float KVs[64 * 64];   // K phase: [d][col]; V phase: [k][c]
    __shared__ float Ps [64 * 64];   // [row][col] probabilities

    const int tid  = threadIdx.x;
    const int lane = tid & 31;
    const int w    = tid >> 5;
    const int q0   = blockIdx.x * 64;
    const int h    = blockIdx.y;
    const int b    = blockIdx.z;

    const float* Qg = g_Qp + (size_t)(b * SS) * DM + h * HD;
    const float* Kg = g_Kp + (size_t)(b * SS) * DM + h * HD;
    const float* Vg = g_Vp + (size_t)(b * SS) * DM + h * HD;

    {   // load Q tile transposed
        const int r   = tid >> 2;
        const int seg = (tid & 3) * 16;
        const float* src = Qg + (size_t)(q0 + r) * DM + seg;
#pragma unroll
        for (int i = 0; i < 4; i++) {
            float4 vv = *(const float4*)(src + i * 4);
            const int dd = seg + i * 4;
            Qst[(dd + 0) * 64 + r] = vv.x;
            Qst[(dd + 1) * 64 + r] = vv.y;
            Qst[(dd + 2) * 64 + r] = vv.z;
            Qst[(dd + 3) * 64 + r] = vv.w;
        }
    }

    float m_r[8], l_r[8], o0[8], o1[8];
#pragma unroll
    for (int i = 0; i < 8; i++) { m_r[i] = -3e38f; l_r[i] = 0.f; o0[i] = 0.f; o1[i] = 0.f; }
    __syncthreads();

    for (int kb = 0; kb < SS; kb += 64) {
        {   // load K tile transposed: KVs[d][col]
            const int r   = tid >> 2;
            const int seg = (tid & 3) * 16;
            const float* src = Kg + (size_t)(kb + r) * DM + seg;
#pragma unroll
            for (int i = 0; i < 4; i++) {
                float4 vv = *(const float4*)(src + i * 4);
                const int dd = seg + i * 4;
                KVs[(dd + 0) * 64 + r] = vv.x;
                KVs[(dd + 1) * 64 + r] = vv.y;
                KVs[(dd + 2) * 64 + r] = vv.z;
                KVs[(dd + 3) * 64 + r] = vv.w;
            }
        }
        const int mk0 = v_mask[b * SS + kb + lane];
        const int mk1 = v_mask[b * SS + kb + lane + 32];
        __syncthreads();

        // S = Q K^T
        float s0[8], s1[8];
#pragma unroll
        for (int i = 0; i < 8; i++) { s0[i] = 0.f; s1[i] = 0.f; }
#pragma unroll 8
        for (int dd = 0; dd < 64; dd++) {
            float a[8];
            *(float4*)(a)     = *(const float4*)&Qst[dd * 64 + w * 8];
            *(float4*)(a + 4) = *(const float4*)&Qst[dd * 64 + w * 8 + 4];
            const float b0 = KVs[dd * 64 + lane];
            const float b1 = KVs[dd * 64 + lane + 32];
#pragma unroll
            for (int i = 0; i < 8; i++) { s0[i] += a[i] * b0; s1[i] += a[i] * b1; }
        }
#pragma unroll
        for (int i = 0; i < 8; i++) {
            s0[i] = mk0 ? s0[i] * 0.125f : -1e12f;
            s1[i] = mk1 ? s1[i] * 0.125f : -1e12f;
        }

        // online softmax; write P to smem
#pragma unroll
        for (int i = 0; i < 8; i++) {
            float mx = fmaxf(s0[i], s1[i]);
#pragma unroll
            for (int off = 16; off > 0; off >>= 1)
                mx = fmaxf(mx, __shfl_xor_sync(0xffffffffu, mx, off));
            const float mn   = fmaxf(m_r[i], mx);
            const float corr = __expf(m_r[i] - mn);
            const float p0   = __expf(s0[i] - mn);
            const float p1   = __expf(s1[i] - mn);
            float sum = p0 + p1;
#pragma unroll
            for (int off = 16; off > 0; off >>= 1)
                sum += __shfl_xor_sync(0xffffffffu, sum, off);
            l_r[i] = l_r[i] * corr + sum;
            m_r[i] = mn;
            o0[i] *= corr;
            o1[i] *= corr;
            Ps[(w * 8 + i) * 64 + lane]      = p0;
            Ps[(w * 8 + i) * 64 + lane + 32] = p1;
        }
        __syncthreads();

        {   // load V tile natural: KVs[k][c]
            const int r   = tid >> 2;
            const int seg = (tid & 3) * 16;
            const float* src = Vg + (size_t)(kb + r) * DM + seg;
            float4* dst = (float4*)&KVs[r * 64 + seg];
#pragma unroll
            for (int i = 0; i < 4; i++) dst[i] = *(const float4*)(src + i * 4);
        }
        __syncthreads();

        // O += P @ V — 4 keys/step: 8 scalar V loads + 8 broadcast LDS.128 of P
#pragma unroll 2
        for (int k4 = 0; k4 < 64; k4 += 4) {
            float b0r[4], b1r[4];
#pragma unroll
            for (int j = 0; j < 4; j++) {
                b0r[j] = KVs[(k4 + j) * 64 + lane];
                b1r[j] = KVs[(k4 + j) * 64 + lane + 32];
            }
#pragma unroll
            for (int i = 0; i < 8; i++) {
                const float4 p4 = *(const float4*)&Ps[(w * 8 + i) * 64 + k4];
                o0[i] += p4.x * b0r[0]; o1[i] += p4.x * b1r[0];
                o0[i] += p4.y * b0r[1]; o1[i] += p4.y * b1r[1];
                o0[i] += p4.z * b0r[2]; o1[i] += p4.z * b1r[2];
                o0[i] += p4.w * b0r[3]; o1[i] += p4.w * b1r[3];
            }
        }
        __syncthreads();
    }

#pragma unroll
    for (int i = 0; i < 8; i++) {
        const float inv = 1.0f / l_r[i];
        const int qr = q0 + w * 8 + i;
        float* op = out + (size_t)(b * SS + qr) * DM + h * HD;
        op[lane]      = o0[i] * inv;
        op[lane + 32] = o1[i] * inv;
    }
}

// ===========================================================================
// Launch
// ===========================================================================
extern "C" void kernel_launch(void* const* d_in, const int* in_sizes, int n_in,
                              void* d_out, int out_size) {
    const float* q  = (const float*)d_in[0];
    const float* k  = (const float*)d_in[1];
    const float* v  = (const float*)d_in[2];
    const int*   vm = (const int*)  d_in[3];
    const float* Wq = (const float*)d_in[4];
    const float* Wk = (const float*)d_in[5];
    const float* Wv = (const float*)d_in[6];
    float* out = (float*)d_out;

    float *Qp = nullptr, *Kp = nullptr, *Vp = nullptr;
    cudaGetSymbolAddress((void**)&Qp, g_Qp);
    cudaGetSymbolAddress((void**)&Kp, g_Kp);
    cudaGetSymbolAddress((void**)&Vp, g_Vp);

    // 1) fp32 -> bf16 hi/lo splits (and W transpose)
    const int nA = (int)(((size_t)3 * MTOT * DM / 4 + 255) / 256);
    split_A<<<nA, 256>>>(q, k, v);
    split_WT<<<dim3(DM / 32, DM / 32, 3), dim3(32, 8)>>>(Wq, Wk, Wv);

    // 2) tensor-core projections
    cudaFuncSetAttribute(gemm_bf16tc,
                         cudaFuncAttributeMaxDynamicSharedMemorySize, GEMM_SMEM);
    gemm_bf16tc<<<dim3(DM / 128, MTOT / 128, 3), 256, GEMM_SMEM>>>(Qp, Kp, Vp);

    // 3) attention
    attn_kernel<<<dim3(SS / 64, NH, BB), 256>>>(vm, out);
}

// round 7
// speedup vs baseline: 3.4184x; 2.5193x over previous
#include <cuda_runtime.h>
#include <cuda_bf16.h>
#include <cstdint>

// Problem constants (fixed shapes from reference_code)
#define BB 2
#define SS 2048
#define DM 1024
#define NH 16
#define HD 64
#define MTOT (BB * SS)   // 4096

// Scratch (static device arrays: allocation-free)
// bf16 hi/lo splits of raw inputs (GEMM A) and transposed weights (GEMM B)
__device__ __nv_bfloat16 g_Ah[3 * MTOT * DM];
__device__ __nv_bfloat16 g_Al[3 * MTOT * DM];
__device__ __nv_bfloat16 g_WTh[3 * DM * DM];
__device__ __nv_bfloat16 g_WTl[3 * DM * DM];
// bf16 hi/lo projected Q/K/V (GEMM outputs, attention inputs): z = 0/1/2
__device__ __nv_bfloat16 g_Ph[3 * MTOT * DM];
__device__ __nv_bfloat16 g_Pl[3 * MTOT * DM];

// ===========================================================================
// PTX helpers
// ===========================================================================
__device__ __forceinline__ uint32_t smem_u32(const void* p) {
    uint32_t a;
    asm("{ .reg .u64 t; cvta.to.shared.u64 t, %1; cvt.u32.u64 %0, t; }"
        : "=r"(a) : "l"(p));
    return a;
}
__device__ __forceinline__ void cp_async16(uint32_t dst, const void* src) {
    asm volatile("cp.async.ca.shared.global [%0], [%1], 16;"
                 :: "r"(dst), "l"(src) : "memory");
}
#define CP_COMMIT() asm volatile("cp.async.commit_group;" ::: "memory")
#define CP_WAIT(n)  asm volatile("cp.async.wait_group %0;" :: "n"(n) : "memory")

__device__ __forceinline__ void ldsm_x4(uint32_t r[4], uint32_t addr) {
    asm volatile("ldmatrix.sync.aligned.m8n8.x4.shared.b16 {%0,%1,%2,%3}, [%4];"
                 : "=r"(r[0]), "=r"(r[1]), "=r"(r[2]), "=r"(r[3]) : "r"(addr));
}
__device__ __forceinline__ void ldsm_x2(uint32_t r[2], uint32_t addr) {
    asm volatile("ldmatrix.sync.aligned.m8n8.x2.shared.b16 {%0,%1}, [%2];"
                 : "=r"(r[0]), "=r"(r[1]) : "r"(addr));
}
__device__ __forceinline__ void ldsm_x2_t(uint32_t r[2], uint32_t addr) {
    asm volatile("ldmatrix.sync.aligned.m8n8.x2.trans.shared.b16 {%0,%1}, [%2];"
                 : "=r"(r[0]), "=r"(r[1]) : "r"(addr));
}
__device__ __forceinline__ void mma_bf16(float d[4], const uint32_t a[4],
                                         const uint32_t b[2]) {
    asm volatile(
        "mma.sync.aligned.m16n8k16.row.col.f32.bf16.bf16.f32 "
        "{%0,%1,%2,%3}, {%4,%5,%6,%7}, {%8,%9}, {%0,%1,%2,%3};"
        : "+f"(d[0]), "+f"(d[1]), "+f"(d[2]), "+f"(d[3])
        : "r"(a[0]), "r"(a[1]), "r"(a[2]), "r"(a[3]), "r"(b[0]), "r"(b[1]));
}
// pack two fp32 -> bf16x2 register (lo -> lower half, hi -> upper half)
__device__ __forceinline__ uint32_t pack_bf16x2(float lo, float hi) {
    uint32_t r;
    asm("cvt.rn.bf16x2.f32 %0, %1, %2;" : "=r"(r) : "f"(hi), "f"(lo));
    return r;
}

// ===========================================================================
// Split pass 1: q/k/v fp32 -> bf16 hi/lo, same layout.
// ===========================================================================
__global__ __launch_bounds__(256)
void split_A(const float* __restrict__ q, const float* __restrict__ k,
             const float* __restrict__ v) {
    const size_t per = (size_t)MTOT * DM / 4;   // float4 count per matrix
    size_t idx = (size_t)blockIdx.x * 256 + threadIdx.x;
    if (idx >= 3 * per) return;
    const int m = (int)(idx / per);
    const size_t off = idx - (size_t)m * per;
    const float4* src = (const float4*)(m == 0 ? q : (m == 1 ? k : v));
    float4 x = src[off];

    __nv_bfloat16 h0 = __float2bfloat16(x.x), h1 = __float2bfloat16(x.y);
    __nv_bfloat16 h2 = __float2bfloat16(x.z), h3 = __float2bfloat16(x.w);
    __nv_bfloat16 l0 = __float2bfloat16(x.x - __bfloat162float(h0));
    __nv_bfloat16 l1 = __float2bfloat16(x.y - __bfloat162float(h1));
    __nv_bfloat16 l2 = __float2bfloat16(x.z - __bfloat162float(h2));
    __nv_bfloat16 l3 = __float2bfloat16(x.w - __bfloat162float(h3));

    __nv_bfloat162* dh = (__nv_bfloat162*)g_Ah;
    __nv_bfloat162* dl = (__nv_bfloat162*)g_Al;
    dh[idx * 2]     = __halves2bfloat162(h0, h1);
    dh[idx * 2 + 1] = __halves2bfloat162(h2, h3);
    dl[idx * 2]     = __halves2bfloat162(l0, l1);
    dl[idx * 2 + 1] = __halves2bfloat162(l2, l3);
}

// ===========================================================================
// Split pass 2: W [K][N] -> W^T [N][K] bf16 hi/lo (tiled smem transpose).
// ===========================================================================
__global__ __launch_bounds__(256)
void split_WT(const float* __restrict__ Wq, const float* __restrict__ Wk,
              const float* __restrict__ Wv) {
    __shared__ float tile[32][33];
    const int z = blockIdx.z;
    const float* W = (z == 0 ? Wq : (z == 1 ? Wk : Wv));
    const int n0 = blockIdx.x * 32;
    const int k0 = blockIdx.y * 32;
    const int tx = threadIdx.x, ty = threadIdx.y;   // (32, 8)

#pragma unroll
    for (int i = 0; i < 4; i++) {
        const int kk = k0 + ty + i * 8;
        tile[ty + i * 8][tx] = W[(size_t)kk * DM + n0 + tx];
    }
    __syncthreads();
    __nv_bfloat16* outh = g_WTh + (size_t)z * DM * DM;
    __nv_bfloat16* outl = g_WTl + (size_t)z * DM * DM;
#pragma unroll
    for (int i = 0; i < 4; i++) {
        const int n = n0 + ty + i * 8;
        const float x = tile[tx][ty + i * 8];
        const __nv_bfloat16 h = __float2bfloat16(x);
        outh[(size_t)n * DM + k0 + tx] = h;
        outl[(size_t)n * DM + k0 + tx] = __float2bfloat16(x - __bfloat162float(h));
    }
}

// ===========================================================================
// Tensor-core projection GEMM (mma.sync bf16 x3 split).
// Writes bf16 hi/lo projected outputs directly (attention consumes bf16).
// ===========================================================================
#define GST   144                     // row stride bytes (64*2 + 16 pad)
#define ARR_B (128 * GST)             // 18432 B per array
#define BUF_B (4 * ARR_B)             // 73728 B per stage
#define GEMM_SMEM (2 * BUF_B)         // 147456

__global__ __launch_bounds__(256)
void gemm_bf16tc() {
    extern __shared__ char smem[];
    const int z = blockIdx.z;
    const __nv_bfloat16* Ah = g_Ah + (size_t)z * MTOT * DM;
    const __nv_bfloat16* Al = g_Al + (size_t)z * MTOT * DM;
    const __nv_bfloat16* Bh = g_WTh + (size_t)z * DM * DM;
    const __nv_bfloat16* Bl = g_WTl + (size_t)z * DM * DM;
    __nv_bfloat16* Ch = g_Ph + (size_t)z * MTOT * DM;
    __nv_bfloat16* Cl = g_Pl + (size_t)z * MTOT * DM;

    const int m0 = blockIdx.y * 128;
    const int n0 = blockIdx.x * 128;
    const int tid = threadIdx.x;
    const int lane = tid & 31;
    const int wid = tid >> 5;
    const int wm = (wid & 1) * 64;
    const int wn = (wid >> 1) * 32;

    const uint32_t sb = smem_u32(smem);
    const int frow = tid >> 3;
    const int fch = tid & 7;

    auto fill = [&](int buf, int kc) {
        const uint32_t b0 = sb + buf * BUF_B;
#pragma unroll
        for (int p = 0; p < 4; p++) {
            const int r = frow + p * 32;
            const uint32_t doff = (uint32_t)(r * GST + fch * 16);
            const size_t ga = (size_t)(m0 + r) * DM + kc + fch * 8;
            const size_t gb = (size_t)(n0 + r) * DM + kc + fch * 8;
            cp_async16(b0 + doff,             Ah + ga);
            cp_async16(b0 + ARR_B + doff,     Al + ga);
            cp_async16(b0 + 2 * ARR_B + doff, Bh + gb);
            cp_async16(b0 + 3 * ARR_B + doff, Bl + gb);
        }
        CP_COMMIT();
    };

    float d[4][4][4];
#pragma unroll
    for (int i = 0; i < 4; i++)
#pragma unroll
        for (int j = 0; j < 4; j++)
#pragma unroll
            for (int r = 0; r < 4; r++) d[i][j][r] = 0.f;

    const int aj = lane >> 3;
    const int arow_in = (aj & 1) * 8 + (lane & 7);
    const int akb = (aj >> 1) * 16;
    const int brow_in = (lane & 7);
    const int bkb = ((lane >> 3) & 1) * 16;

    fill(0, 0);
    int buf = 0;
    for (int s = 0; s < DM / 64; s++) {
        if (s + 1 < DM / 64) {
            fill(buf ^ 1, (s + 1) * 64);
            CP_WAIT(1);
        } else {
            CP_WAIT(0);
        }
        __syncthreads();

        const uint32_t base = sb + buf * BUF_B;
#pragma unroll
        for (int ks = 0; ks < 4; ks++) {
            const int k0b = ks * 32;
            uint32_t ah[4][4], al[4][4], bh[4][2], bl[4][2];
#pragma unroll
            for (int mt = 0; mt < 4; mt++) {
                const uint32_t aoff =
                    (uint32_t)((wm + mt * 16 + arow_in) * GST + k0b + akb);
                ldsm_x4(ah[mt], base + aoff);
                ldsm_x4(al[mt], base + ARR_B + aoff);
            }
#pragma unroll
            for (int nt = 0; nt < 4; nt++) {
                const uint32_t boff =
                    (uint32_t)((wn + nt * 8 + brow_in) * GST + k0b + bkb);
                ldsm_x2(bh[nt], base + 2 * ARR_B + boff);
                ldsm_x2(bl[nt], base + 3 * ARR_B + boff);
            }
#pragma unroll
            for (int mt = 0; mt < 4; mt++)
#pragma unroll
                for (int nt = 0; nt < 4; nt++) {
                    mma_bf16(d[mt][nt], ah[mt], bh[nt]);
                    mma_bf16(d[mt][nt], ah[mt], bl[nt]);
                    mma_bf16(d[mt][nt], al[mt], bh[nt]);
                }
        }
        __syncthreads();
        buf ^= 1;
    }

    // epilogue: split fp32 acc -> bf16 hi + lo and store pairs
    const int g = lane >> 2;
    const int t2 = (lane & 3) * 2;
#pragma unroll
    for (int mt = 0; mt < 4; mt++) {
#pragma unroll
        for (int nt = 0; nt < 4; nt++) {
            const int row0 = m0 + wm + mt * 16 + g;
            const int col = n0 + wn + nt * 8 + t2;
#pragma unroll
            for (int rr = 0; rr < 2; rr++) {
                const float a = d[mt][nt][rr * 2];
                const float bvl = d[mt][nt][rr * 2 + 1];
                const __nv_bfloat16 ha = __float2bfloat16(a);
                const __nv_bfloat16 hb = __float2bfloat16(bvl);
                const size_t o = (size_t)(row0 + rr * 8) * DM + col;
                *(__nv_bfloat162*)(Ch + o) = __halves2bfloat162(ha, hb);
                *(__nv_bfloat162*)(Cl + o) = __halves2bfloat162(
                    __float2bfloat16(a - __bfloat162float(ha)),
                    __float2bfloat16(bvl - __bfloat162float(hb)));
            }
        }
    }
}

// ===========================================================================
// Tensor-core flash attention. CTA = 128 threads (4 warps) per
// (b, h, 64 q rows). Warp w owns q rows w*16..w*16+15 and all 64 keys of a
// block. Q fragments register-cached; K/V bf16 hi/lo tiles in smem.
// S = QK^T and O += P V via mma.sync bf16 with 3-term hi/lo splits.
// ===========================================================================
#define AST 72                        // bf16 per smem row (64 + 8 pad) = 144B

__global__ __launch_bounds__(128)
void attn_tc(const int* __restrict__ v_mask, float* __restrict__ out) {
    __shared__ __nv_bfloat16 sKh[64 * AST];
    __shared__ __nv_bfloat16 sKl[64 * AST];
    __shared__ __nv_bfloat16 sVh[64 * AST];
    __shared__ __nv_bfloat16 sVl[64 * AST];
    __shared__ int smask[64];

    const int tid  = threadIdx.x;
    const int lane = tid & 31;
    const int w    = tid >> 5;          // 0..3
    const int q0   = blockIdx.x * 64;
    const int h    = blockIdx.y;
    const int b    = blockIdx.z;
    const int g    = lane >> 2;         // fragment row within 8
    const int t    = lane & 3;          // fragment col pair

    const size_t ho = (size_t)h * HD;
    const __nv_bfloat16* Qh_g = g_Ph + ((size_t)(b * SS)) * DM + ho;
    const __nv_bfloat16* Ql_g = g_Pl + ((size_t)(b * SS)) * DM + ho;
    const __nv_bfloat16* Kh_g = g_Ph + ((size_t)MTOT + b * SS) * DM + ho;
    const __nv_bfloat16* Kl_g = g_Pl + ((size_t)MTOT + b * SS) * DM + ho;
    const __nv_bfloat16* Vh_g = g_Ph + ((size_t)2 * MTOT + b * SS) * DM + ho;
    const __nv_bfloat16* Vl_g = g_Pl + ((size_t)2 * MTOT + b * SS) * DM + ho;

    const uint32_t sbKh = smem_u32(sKh), sbKl = smem_u32(sKl);
    const uint32_t sbVh = smem_u32(sVh), sbVl = smem_u32(sVl);

    // ---- Q phase: stage Qh/Ql through the K smem regions, grab fragments ----
#pragma unroll
    for (int i = 0; i < 8; i++) {
        const int c = tid + i * 128;          // 0..1023
        const int tile = c >> 9;              // 0: Qh, 1: Ql
        const int cc = c & 511;
        const int row = cc >> 3;
        const int ch = cc & 7;
        const __nv_bfloat16* src =
            (tile ? Ql_g : Qh_g) + (size_t)(q0 + row) * DM + ch * 8;
        cp_async16((tile ? sbKl : sbKh) + row * 144 + ch * 16, src);
    }
    CP_COMMIT(); CP_WAIT(0);
    __syncthreads();

    uint32_t qh[4][4], ql[4][4];
    const uint32_t qrowoff = (uint32_t)((w * 16 + (lane & 15)) * 144);
    const uint32_t qcoloff = (uint32_t)(((lane >> 4) & 1) * 16);
#pragma unroll
    for (int kc = 0; kc < 4; kc++) {
        ldsm_x4(qh[kc], sbKh + qrowoff + kc * 32 + qcoloff);
        ldsm_x4(ql[kc], sbKl + qrowoff + kc * 32 + qcoloff);
    }
    __syncthreads();

    float o[8][4];
#pragma unroll
    for (int j = 0; j < 8; j++)
#pragma unroll
        for (int r = 0; r < 4; r++) o[j][r] = 0.f;
    float m0 = -3e38f, m1 = -3e38f, l0 = 0.f, l1 = 0.f;

    // ldmatrix address components
    const uint32_t krow = (uint32_t)((lane & 7) * 144);
    const uint32_t kcol = (uint32_t)(((lane >> 3) & 1) * 16);
    const uint32_t vrow = (uint32_t)((lane & 15) * 144);

    for (int kb = 0; kb < SS; kb += 64) {
        // ---- stage K/V hi/lo tiles + mask ----
#pragma unroll
        for (int i = 0; i < 16; i++) {
            const int c = tid + i * 128;      // 0..2047
            const int tile = c >> 9;          // 0:Kh 1:Kl 2:Vh 3:Vl
            const int cc = c & 511;
            const int row = cc >> 3;
            const int ch = cc & 7;
            const __nv_bfloat16* src =
                (tile == 0 ? Kh_g : tile == 1 ? Kl_g : tile == 2 ? Vh_g : Vl_g)
                + (size_t)(kb + row) * DM + ch * 8;
            const uint32_t dst =
                (tile == 0 ? sbKh : tile == 1 ? sbKl : tile == 2 ? sbVh : sbVl)
                + row * 144 + ch * 16;
            cp_async16(dst, src);
        }
        if (tid < 16)
            ((int4*)smask)[tid] = *(const int4*)(v_mask + b * SS + kb + tid * 4);
        CP_COMMIT(); CP_WAIT(0);
        __syncthreads();

        // ---- S = Q K^T (bf16 x3) ----
        float s[8][4];
#pragma unroll
        for (int j = 0; j < 8; j++)
#pragma unroll
            for (int r = 0; r < 4; r++) s[j][r] = 0.f;
#pragma unroll
        for (int kc = 0; kc < 4; kc++) {
#pragma unroll
            for (int j = 0; j < 8; j++) {
                uint32_t kh2[2], kl2[2];
                const uint32_t ao = (uint32_t)(j * 8 * 144) + krow + kc * 32 + kcol;
                ldsm_x2(kh2, sbKh + ao);
                ldsm_x2(kl2, sbKl + ao);
                mma_bf16(s[j], qh[kc], kh2);
                mma_bf16(s[j], qh[kc], kl2);
                mma_bf16(s[j], ql[kc], kh2);
            }
        }

        // ---- mask + scale (exact -1e12 for masked cols) ----
#pragma unroll
        for (int j = 0; j < 8; j++) {
            const int mk0 = smask[j * 8 + 2 * t];
            const int mk1 = smask[j * 8 + 2 * t + 1];
            s[j][0] = mk0 ? s[j][0] * 0.125f : -1e12f;
            s[j][1] = mk1 ? s[j][1] * 0.125f : -1e12f;
            s[j][2] = mk0 ? s[j][2] * 0.125f : -1e12f;
            s[j][3] = mk1 ? s[j][3] * 0.125f : -1e12f;
        }

        // ---- online softmax on fragment layout (quad reductions) ----
        float mx0 = -3e38f, mx1 = -3e38f;
#pragma unroll
        for (int j = 0; j < 8; j++) {
            mx0 = fmaxf(mx0, fmaxf(s[j][0], s[j][1]));
            mx1 = fmaxf(mx1, fmaxf(s[j][2], s[j][3]));
        }
        mx0 = fmaxf(mx0, __shfl_xor_sync(0xffffffffu, mx0, 1));
        mx0 = fmaxf(mx0, __shfl_xor_sync(0xffffffffu, mx0, 2));
        mx1 = fmaxf(mx1, __shfl_xor_sync(0xffffffffu, mx1, 1));
        mx1 = fmaxf(mx1, __shfl_xor_sync(0xffffffffu, mx1, 2));

        const float mn0 = fmaxf(m0, mx0), mn1 = fmaxf(m1, mx1);
        const float c0 = __expf(m0 - mn0), c1 = __expf(m1 - mn1);
        float sum0 = 0.f, sum1 = 0.f;
#pragma unroll
        for (int j = 0; j < 8; j++) {
            s[j][0] = __expf(s[j][0] - mn0);
            s[j][1] = __expf(s[j][1] - mn0);
            s[j][2] = __expf(s[j][2] - mn1);
            s[j][3] = __expf(s[j][3] - mn1);
            sum0 += s[j][0] + s[j][1];
            sum1 += s[j][2] + s[j][3];
        }
        sum0 += __shfl_xor_sync(0xffffffffu, sum0, 1);
        sum0 += __shfl_xor_sync(0xffffffffu, sum0, 2);
        sum1 += __shfl_xor_sync(0xffffffffu, sum1, 1);
        sum1 += __shfl_xor_sync(0xffffffffu, sum1, 2);
        l0 = l0 * c0 + sum0; l1 = l1 * c1 + sum1;
        m0 = mn0; m1 = mn1;
#pragma unroll
        for (int j = 0; j < 8; j++) {
            o[j][0] *= c0; o[j][1] *= c0;
            o[j][2] *= c1; o[j][3] *= c1;
        }

        // ---- O += P V (P hi/lo from registers, V via ldmatrix.trans) ----
#pragma unroll
        for (int kc = 0; kc < 4; kc++) {
            const int j0 = 2 * kc, j1 = 2 * kc + 1;
            uint32_t pah[4], pal[4];
            {
                const float* ps[4] = {s[j0], s[j0] + 2, s[j1], s[j1] + 2};
#pragma unroll
                for (int r = 0; r < 4; r++) {
                    const float a = ps[r][0], bv = ps[r][1];
                    const __nv_bfloat16 ha = __float2bfloat16(a);
                    const __nv_bfloat16 hb = __float2bfloat16(bv);
                    __nv_bfloat162 hp = __halves2bfloat162(ha, hb);
                    pah[r] = *reinterpret_cast<uint32_t*>(&hp);
                    pal[r] = pack_bf16x2(a - __bfloat162float(ha),
                                         bv - __bfloat162float(hb));
                }
            }
#pragma unroll
            for (int j2 = 0; j2 < 8; j2++) {
                uint32_t vh2[2], vl2[2];
                const uint32_t ao = (uint32_t)(kc * 16 * 144) + vrow + j2 * 16;
                ldsm_x2_t(vh2, sbVh + ao);
                ldsm_x2_t(vl2, sbVl + ao);
                mma_bf16(o[j2], pah, vh2);
                mma_bf16(o[j2], pah, vl2);
                mma_bf16(o[j2], pal, vh2);
            }
        }
        __syncthreads();
    }

    // ---- epilogue ----
    const float inv0 = 1.0f / l0, inv1 = 1.0f / l1;
    const int r0 = q0 + w * 16 + g;
    float* op0 = out + ((size_t)(b * SS) + r0) * DM + ho + 2 * t;
    float* op1 = op0 + (size_t)8 * DM;
#pragma unroll
    for (int j2 = 0; j2 < 8; j2++) {
        *(float2*)(op0 + j2 * 8) = make_float2(o[j2][0] * inv0, o[j2][1] * inv0);
        *(float2*)(op1 + j2 * 8) = make_float2(o[j2][2] * inv1, o[j2][3] * inv1);
    }
}

// ===========================================================================
// Launch
// ===========================================================================
extern "C" void kernel_launch(void* const* d_in, const int* in_sizes, int n_in,
                              void* d_out, int out_size) {
    const float* q  = (const float*)d_in[0];
    const float* k  = (const float*)d_in[1];
    const float* v  = (const float*)d_in[2];
    const int*   vm = (const int*)  d_in[3];
    const float* Wq = (const float*)d_in[4];
    const float* Wk = (const float*)d_in[5];
    const float* Wv = (const float*)d_in[6];
    float* out = (float*)d_out;

    // 1) fp32 -> bf16 hi/lo splits (and W transpose)
    const int nA = (int)(((size_t)3 * MTOT * DM / 4 + 255) / 256);
    split_A<<<nA, 256>>>(q, k, v);
    split_WT<<<dim3(DM / 32, DM / 32, 3), dim3(32, 8)>>>(Wq, Wk, Wv);

    // 2) tensor-core projections (write bf16 hi/lo directly)
    cudaFuncSetAttribute(gemm_bf16tc,
                         cudaFuncAttributeMaxDynamicSharedMemorySize, GEMM_SMEM);
    gemm_bf16tc<<<dim3(DM / 128, MTOT / 128, 3), 256, GEMM_SMEM>>>();

    // 3) tensor-core attention
    attn_tc<<<dim3(SS / 64, NH, BB), 128>>>(vm, out);
}